// round 9
// baseline (speedup 1.0000x reference)
#include <cuda_runtime.h>
#include <cuda_fp16.h>
#include <math.h>
#include <stdint.h>

#define D_MODEL 1024
#define D_INNER 2048
#define D_STATE 16
#define DT_RANK 64
#define NB 2
#define TSEQ 2048
#define MROWS (NB*TSEQ)   /* 4096 */
#define EPSV 1e-6f

typedef __half fp16;

// ---------------- scratch (no allocations allowed) ----------------
__device__ fp16  g_xnh[MROWS*D_MODEL];
__device__ fp16  g_inwh[2*D_INNER*D_MODEL];
__device__ fp16  g_xpwh[96*D_INNER],    g_xpwl[96*D_INNER];
__device__ fp16  g_dtwh[D_INNER*DT_RANK], g_dtwl[D_INNER*DT_RANK];
__device__ fp16  g_opwh[D_MODEL*D_INNER];
__device__ float g_xzx[MROWS*D_INNER];          // x-half of in_proj, fp32
__device__ fp16  g_sg[MROWS*D_INNER];           // silu(z), fp16
__device__ fp16  g_xch[MROWS*D_INNER],  g_xcl[MROWS*D_INNER];
__device__ float g_xdbc[MROWS*96];
__device__ fp16  g_dth[MROWS*DT_RANK],  g_dtl[MROWS*DT_RANK];
__device__ float g_dc[MROWS*D_INNER],   g_du[MROWS*D_INNER];
__device__ fp16  g_yh[MROWS*D_INNER];

// ---------------- helpers ----------------
__device__ __forceinline__ uint32_t s2u(const void* p) {
    uint32_t a;
    asm("{ .reg .u64 t; cvta.to.shared.u64 t, %1; cvt.u32.u64 %0, t; }" : "=r"(a) : "l"(p));
    return a;
}
__device__ __forceinline__ void cpa16(uint32_t dst, const void* src) {
    asm volatile("cp.async.cg.shared.global [%0], [%1], 16;" :: "r"(dst), "l"(src) : "memory");
}
__device__ __forceinline__ void cpa16z(uint32_t dst, const void* src, int sz) {
    asm volatile("cp.async.cg.shared.global [%0], [%1], 16, %2;" :: "r"(dst), "l"(src), "r"(sz) : "memory");
}
#define CPA_COMMIT() asm volatile("cp.async.commit_group;" ::: "memory")

#define LDSM4(r, a) \
    asm volatile("ldmatrix.sync.aligned.m8n8.x4.shared.b16 {%0,%1,%2,%3}, [%4];" \
        : "=r"((r)[0]),"=r"((r)[1]),"=r"((r)[2]),"=r"((r)[3]) : "r"(a))

#define MMA16816(d, a, b0, b1) \
    asm volatile("mma.sync.aligned.m16n8k16.row.col.f32.f16.f16.f32 " \
        "{%0,%1,%2,%3}, {%4,%5,%6,%7}, {%8,%9}, {%0,%1,%2,%3};" \
        : "+f"((d)[0]),"+f"((d)[1]),"+f"((d)[2]),"+f"((d)[3]) \
        : "r"((a)[0]),"r"((a)[1]),"r"((a)[2]),"r"((a)[3]), "r"(b0),"r"(b1))

// ---------------- split-fp16 GEMM via mma.sync ----------------
// 128x128 tile, BK=64, 3-stage ring (96KB) -> 2 CTAs/SM, 8 warps (2x4).
// EPI 0: xzx fp32 (n<2048) + silu->sg fp16 (n>=2048)
// EPI 1: dt epi (bias+softplus+clip -> dc; du = dc * fp16 xch)
// EPI 2: C=v+res   EPI 4: atomicAdd (split-K)
#define GSMEM (3 * 32768)
template<int EPI, int TERMS>
__global__ __launch_bounds__(256, 2)
void gemm_mma(const fp16* __restrict__ Ah, const fp16* __restrict__ Al,
              const fp16* __restrict__ Bh, const fp16* __restrict__ Bl,
              int K, int Nreal, int ldc,
              float* __restrict__ o0, float* __restrict__ o1,
              const float* __restrict__ e0, const fp16* __restrict__ e1h,
              fp16* __restrict__ osg)
{
    extern __shared__ char dyn[];
    const uint32_t sbase = s2u(dyn);
    const int tid = threadIdx.x, lane = tid & 31, wid = tid >> 5;
    const int wm = wid >> 2, wn = wid & 3;
    const int m0 = blockIdx.y * 128, n0 = blockIdx.x * 128;
    const int NCtot = TERMS * K / 64;
    const int per = (NCtot + gridDim.z - 1) / gridDim.z;
    const int kc0 = blockIdx.z * per;
    const int kc1 = min(NCtot, kc0 + per);

    float acc[4][4][4];
    #pragma unroll
    for (int i = 0; i < 4; i++)
        #pragma unroll
        for (int j = 0; j < 4; j++)
            #pragma unroll
            for (int k = 0; k < 4; k++) acc[i][j][k] = 0.f;

    auto load_stage = [&](int s, int kc) {
        int kb = kc * 64;
        int seg = (TERMS == 1) ? 0 : kb / K;
        int kk = kb - seg * K;
        const fp16* Asrc = (seg == 1) ? Al : Ah;
        const fp16* Bsrc = (seg == 2) ? Bl : Bh;
        uint32_t st = sbase + s * 32768;
        #pragma unroll
        for (int j = 0; j < 4; j++) {
            int idx = tid + j * 256;
            int r = idx >> 3, c = idx & 7;
            cpa16(st + r * 128 + ((c ^ (r & 7)) * 16),
                  Asrc + (size_t)(m0 + r) * K + kk + c * 8);
        }
        uint32_t sb = st + 16384;
        #pragma unroll
        for (int j = 0; j < 4; j++) {
            int idx = tid + j * 256;
            int r = idx >> 3, c = idx & 7;
            int nr = n0 + r;
            int ok = nr < Nreal;
            cpa16z(sb + r * 128 + ((c ^ (r & 7)) * 16),
                   Bsrc + (size_t)(ok ? nr : 0) * K + kk + c * 8, ok ? 16 : 0);
        }
    };

    if (kc0 < kc1)     load_stage(0, kc0);
    CPA_COMMIT();
    if (kc0 + 1 < kc1) load_stage(1, kc0 + 1);
    CPA_COMMIT();

    for (int kc = kc0; kc < kc1; kc++) {
        int i = kc - kc0;
        int s = i % 3;
        asm volatile("cp.async.wait_group 1;" ::: "memory");
        __syncthreads();
        if (kc + 2 < kc1) load_stage((i + 2) % 3, kc + 2);
        CPA_COMMIT();

        uint32_t sA = sbase + s * 32768;
        uint32_t sB = sA + 16384;
        #pragma unroll
        for (int ks = 0; ks < 4; ks++) {
            uint32_t a[4][4], b[2][4];
            #pragma unroll
            for (int mi = 0; mi < 4; mi++) {
                int r = wm * 64 + mi * 16 + (lane & 15);
                int c = (2 * ks + (lane >> 4)) ^ (r & 7);
                LDSM4(a[mi], sA + r * 128 + c * 16);
            }
            #pragma unroll
            for (int g = 0; g < 2; g++) {
                int r = wn * 32 + g * 16 + (lane & 7) + ((lane >> 4) & 1) * 8;
                int c = (2 * ks + ((lane >> 3) & 1)) ^ (r & 7);
                LDSM4(b[g], sB + r * 128 + c * 16);
            }
            #pragma unroll
            for (int mi = 0; mi < 4; mi++)
                #pragma unroll
                for (int nj = 0; nj < 4; nj++) {
                    int bg = nj >> 1, br = (nj & 1) * 2;
                    MMA16816(acc[mi][nj], a[mi], b[bg][br], b[bg][br+1]);
                }
        }
    }

    // ---- epilogue straight from registers ----
    #pragma unroll
    for (int mi = 0; mi < 4; mi++)
        #pragma unroll
        for (int nj = 0; nj < 4; nj++)
            #pragma unroll
            for (int h = 0; h < 2; h++) {
                int m = m0 + wm*64 + mi*16 + (lane >> 2) + h*8;
                int nb = n0 + wn*32 + nj*8 + (lane & 3)*2;
                float vx = acc[mi][nj][h*2], vy = acc[mi][nj][h*2+1];
                size_t ci = (size_t)m * ldc + nb;
                if (EPI == 0) {
                    if (nb < D_INNER) {
                        *(float2*)(o0 + (size_t)m * D_INNER + nb) = make_float2(vx, vy);
                    } else {
                        float sx_ = vx / (1.f + __expf(-vx));
                        float sy_ = vy / (1.f + __expf(-vy));
                        __half2 hv; hv.x = __float2half(sx_); hv.y = __float2half(sy_);
                        *(__half2*)(osg + (size_t)m * D_INNER + nb - D_INNER) = hv;
                    }
                } else if (EPI == 1) {
                    vx += e0[nb]; vy += e0[nb+1];
                    float spx = (vx > 20.f) ? vx : log1pf(__expf(vx));
                    float spy = (vy > 20.f) ? vy : log1pf(__expf(vy));
                    float dx = fminf(fmaxf(spx, -10.f), 1.f);
                    float dy = fminf(fmaxf(spy, -10.f), 1.f);
                    __half2 ev2 = *(const __half2*)(e1h + ci);
                    *(float2*)(o0 + ci) = make_float2(dx, dy);
                    *(float2*)(o1 + ci) = make_float2(dx * __half2float(ev2.x),
                                                     dy * __half2float(ev2.y));
                } else if (EPI == 2) {
                    float2 rv = *(const float2*)(e0 + ci);
                    *(float2*)(o0 + ci) = make_float2(vx + rv.x, vy + rv.y);
                } else {
                    if (nb < Nreal) {
                        atomicAdd(o0 + ci, vx);
                        atomicAdd(o0 + ci + 1, vy);
                    }
                }
            }
}

// ---------------- fused init: wprep + zero(xdbc) + rmsnorm in ONE launch ----------------
#define C1 (2*D_INNER*D_MODEL/4)
#define C2 (C1 + D_MODEL*D_INNER/4)
#define C3 (C2 + 96*D_INNER/4)
#define C4 (C3 + D_INNER*DT_RANK/4)
#define WPB ((C4 + 255) / 256)          /* 6464 */
#define ZB  ((MROWS*96) / 256)          /* 1536 */
__global__ void init_fused(const float4* __restrict__ w_in,
                           const float4* __restrict__ w_op,
                           const float4* __restrict__ w_xp,
                           const float4* __restrict__ w_dt,
                           const float* __restrict__ x,
                           const float* __restrict__ w_norm) {
    __shared__ float red[8];
    __shared__ float sscale;
    int bx = blockIdx.x;
    if (bx < WPB) {
        int i = bx * 256 + threadIdx.x;
        if (i >= C4) return;
        const float4* src;
        fp16 *hi, *lo = nullptr;
        int j = i;
        if (i < C1)      { src = w_in; hi = g_inwh; }
        else if (i < C2) { src = w_op; hi = g_opwh; j = i - C1; }
        else if (i < C3) { src = w_xp; hi = g_xpwh; lo = g_xpwl; j = i - C2; }
        else             { src = w_dt; hi = g_dtwh; lo = g_dtwl; j = i - C3; }
        float4 v = src[j];
        fp16 h0 = __float2half(v.x), h1 = __float2half(v.y);
        fp16 h2 = __float2half(v.z), h3 = __float2half(v.w);
        __half2 p0, p1;
        p0.x = h0; p0.y = h1; p1.x = h2; p1.y = h3;
        *(__half2*)(hi + (size_t)j * 4)     = p0;
        *(__half2*)(hi + (size_t)j * 4 + 2) = p1;
        if (lo) {
            __half2 q0, q1;
            q0.x = __float2half(v.x - __half2float(h0));
            q0.y = __float2half(v.y - __half2float(h1));
            q1.x = __float2half(v.z - __half2float(h2));
            q1.y = __float2half(v.w - __half2float(h3));
            *(__half2*)(lo + (size_t)j * 4)     = q0;
            *(__half2*)(lo + (size_t)j * 4 + 2) = q1;
        }
    } else if (bx < WPB + ZB) {
        int i = (bx - WPB) * 256 + threadIdx.x;
        g_xdbc[i] = 0.f;
    } else {
        int row = bx - WPB - ZB;
        int tid = threadIdx.x;
        const float4* xr = (const float4*)(x + (size_t)row * D_MODEL);
        float4 v = xr[tid];
        float ss = v.x*v.x + v.y*v.y + v.z*v.z + v.w*v.w;
        #pragma unroll
        for (int off = 16; off > 0; off >>= 1)
            ss += __shfl_xor_sync(0xffffffffu, ss, off);
        int lane = tid & 31, wq = tid >> 5;
        if (lane == 0) red[wq] = ss;
        __syncthreads();
        if (tid == 0) {
            float t = 0.f;
            #pragma unroll
            for (int i2 = 0; i2 < 8; i2++) t += red[i2];
            sscale = rsqrtf(t * (1.0f / D_MODEL) + EPSV);
        }
        __syncthreads();
        float sc = sscale;
        float4 wv = ((const float4*)w_norm)[tid];
        float o0 = v.x*sc*wv.x, o1 = v.y*sc*wv.y, o2 = v.z*sc*wv.z, o3 = v.w*sc*wv.w;
        size_t base = (size_t)row * D_MODEL + tid * 4;
        __half2 ph0, ph1;
        ph0.x = __float2half(o0); ph0.y = __float2half(o1);
        ph1.x = __float2half(o2); ph1.y = __float2half(o3);
        *(__half2*)(g_xnh+base)   = ph0; *(__half2*)(g_xnh+base+2) = ph1;
    }
}

__global__ void dtsplit_kernel() {
    int i = blockIdx.x * 256 + threadIdx.x;
    if (i >= MROWS * DT_RANK) return;
    int m = i >> 6, n = i & 63;
    float v = g_xdbc[(size_t)m * 96 + n];
    fp16 h = __float2half(v);
    g_dth[i] = h;
    g_dtl[i] = __float2half(v - __half2float(h));
}

// ---------------- tiled depthwise causal conv(4) + silu -> fp16 hi/lo ----------------
// block = 64 t-rows x 128 channels; smem-staged input (read amplification 1x).
__global__ __launch_bounds__(256) void conv_tiled(const float* __restrict__ cw,
                                                  const float* __restrict__ cb) {
    __shared__ float sx[67*128];
    int db = blockIdx.x & 15, tb = blockIdx.x >> 4;
    int t0 = tb * 64;
    int d0 = db * 128;
    int tid = threadIdx.x;
    for (int idx = tid; idx < 67*32; idx += 256) {
        int r = idx >> 5, c = idx & 31;
        int bt = t0 - 3 + r;
        int btc = bt < 0 ? 0 : bt;
        *(float4*)&sx[r*128 + c*4] =
            *(const float4*)(g_xzx + (size_t)btc * D_INNER + d0 + c*4);
    }
    __syncthreads();
    int j = tid & 31;
    int i0 = (tid >> 5) * 8;
    int d = d0 + j*4;
    float wv[4][4];
    *(float4*)wv[0] = *(const float4*)(cw + (d+0)*4);
    *(float4*)wv[1] = *(const float4*)(cw + (d+1)*4);
    *(float4*)wv[2] = *(const float4*)(cw + (d+2)*4);
    *(float4*)wv[3] = *(const float4*)(cw + (d+3)*4);
    float4 bvv = *(const float4*)(cb + d);
    #pragma unroll
    for (int rep = 0; rep < 8; rep++) {
        int i = i0 + rep;
        int tin = (t0 + i) & (TSEQ - 1);
        float a0 = bvv.x, a1 = bvv.y, a2 = bvv.z, a3 = bvv.w;
        #pragma unroll
        for (int k = 0; k < 4; k++) {
            if (tin - 3 + k < 0) continue;
            float4 xv = *(float4*)&sx[(i+k)*128 + j*4];
            a0 = fmaf(wv[0][k], xv.x, a0);
            a1 = fmaf(wv[1][k], xv.y, a1);
            a2 = fmaf(wv[2][k], xv.z, a2);
            a3 = fmaf(wv[3][k], xv.w, a3);
        }
        float o0 = a0/(1.f+__expf(-a0)), o1 = a1/(1.f+__expf(-a1));
        float o2 = a2/(1.f+__expf(-a2)), o3 = a3/(1.f+__expf(-a3));
        size_t base = (size_t)(t0 + i) * D_INNER + d;
        fp16 h0=__float2half(o0), h1=__float2half(o1), h2=__float2half(o2), h3=__float2half(o3);
        __half2 ph0, ph1, pl0, pl1;
        ph0.x=h0; ph0.y=h1; ph1.x=h2; ph1.y=h3;
        pl0.x=__float2half(o0-__half2float(h0));
        pl0.y=__float2half(o1-__half2float(h1));
        pl1.x=__float2half(o2-__half2float(h2));
        pl1.y=__float2half(o3-__half2float(h3));
        *(__half2*)(g_xch+base)   = ph0; *(__half2*)(g_xch+base+2) = ph1;
        *(__half2*)(g_xcl+base)   = pl0; *(__half2*)(g_xcl+base+2) = pl1;
    }
}

// ---------------- selective scan: latency-optimized, 32-step sub-blocks ----------------
__global__ __launch_bounds__(256) void scan_kernel(const float* __restrict__ A_log,
                                                   const float* __restrict__ Dp) {
    __shared__ float sB[64*16], sC[64*16], sdc[64*16], sdu[64*16];
    __shared__ float se[64*16], sg[64*16];
    __shared__ float sP[32*16*20];        // [t32][cl][s] pad 20 (float4-able)
    int bid = blockIdx.x;
    int b = bid >> 7;
    int d0 = (bid & 127) << 4;
    int tid = threadIdx.x;
    int w = tid >> 5, lane = tid & 31;
    int s = lane & 15, half = lane >> 4;
    int cl = w * 2 + half;
    int d = d0 + cl;
    int jlo = tid & 15;
    float Aval = -__expf(A_log[d * D_STATE + s]);
    float Dvj = Dp[d0 + jlo];
    float h = 0.f;

    for (int t0 = 0; t0 < TSEQ; t0 += 64) {
        for (int i = tid; i < 1024; i += 256) {
            int ti = i >> 4, j = i & 15;
            size_t row = (size_t)b * TSEQ + t0 + ti;
            sB[i]  = g_xdbc[row * 96 + 64 + j];
            sC[i]  = g_xdbc[row * 96 + 80 + j];
            sdc[i] = g_dc[row * D_INNER + d0 + j];
            sdu[i] = g_du[row * D_INNER + d0 + j];
            se[i]  = __half2float(g_xch[row * D_INNER + d0 + j]) * Dvj;
            sg[i]  = __half2float(g_sg[row * D_INNER + d0 + j]);
        }
        __syncthreads();
        #pragma unroll
        for (int sub = 0; sub < 2; sub++) {
            #pragma unroll
            for (int i = 0; i < 32; i++) {
                int t = sub * 32 + i;
                float dcv = sdc[t*16 + cl];
                float duv = sdu[t*16 + cl];
                float r = __expf(dcv * Aval);
                h = fmaf(r, h, duv * sB[t*16 + s]);
                sP[(i*16 + cl)*20 + s] = h * sC[t*16 + s];
            }
            __syncthreads();
            #pragma unroll
            for (int rep = 0; rep < 2; rep++) {
                int idx = tid + rep * 256;
                int tl = idx >> 4, clr = idx & 15;
                const float4* p4 = (const float4*)&sP[(tl*16 + clr)*20];
                float4 va = p4[0], vb = p4[1], vc = p4[2], vd = p4[3];
                float p = va.x+va.y+va.z+va.w + vb.x+vb.y+vb.z+vb.w
                        + vc.x+vc.y+vc.z+vc.w + vd.x+vd.y+vd.z+vd.w;
                int t = sub * 32 + tl;
                float yv = (p + se[t*16 + clr]) * sg[t*16 + clr];
                size_t row = (size_t)b * TSEQ + t0 + t;
                g_yh[row * D_INNER + d0 + clr] = __float2half(yv);
            }
            __syncthreads();
        }
    }
}

// ---------------- launch ----------------
extern "C" void kernel_launch(void* const* d_in, const int* in_sizes, int n_in,
                              void* d_out, int out_size) {
    (void)in_sizes; (void)n_in; (void)out_size;
    const float* x          = (const float*)d_in[0];
    const float* in_proj_w  = (const float*)d_in[1];
    const float* conv_w     = (const float*)d_in[2];
    const float* conv_b     = (const float*)d_in[3];
    const float* x_proj_w   = (const float*)d_in[4];
    const float* dt_proj_w  = (const float*)d_in[5];
    const float* dt_proj_b  = (const float*)d_in[6];
    const float* A_log      = (const float*)d_in[7];
    const float* Dp         = (const float*)d_in[8];
    const float* out_proj_w = (const float*)d_in[9];
    const float* norm_w     = (const float*)d_in[10];
    float* out = (float*)d_out;

    fp16 *xnh, *inwh, *xpwh, *xpwl, *dtwh, *dtwl, *opwh;
    fp16 *xch, *xcl, *dth, *dtl, *yh, *sgp;
    float *xzx, *xdbc, *dcb, *dub;
    cudaGetSymbolAddress((void**)&xnh,  g_xnh);
    cudaGetSymbolAddress((void**)&inwh, g_inwh);
    cudaGetSymbolAddress((void**)&xpwh, g_xpwh); cudaGetSymbolAddress((void**)&xpwl, g_xpwl);
    cudaGetSymbolAddress((void**)&dtwh, g_dtwh); cudaGetSymbolAddress((void**)&dtwl, g_dtwl);
    cudaGetSymbolAddress((void**)&opwh, g_opwh);
    cudaGetSymbolAddress((void**)&xch,  g_xch);  cudaGetSymbolAddress((void**)&xcl,  g_xcl);
    cudaGetSymbolAddress((void**)&dth,  g_dth);  cudaGetSymbolAddress((void**)&dtl,  g_dtl);
    cudaGetSymbolAddress((void**)&yh,   g_yh);   cudaGetSymbolAddress((void**)&sgp,  g_sg);
    cudaGetSymbolAddress((void**)&xzx,  g_xzx);
    cudaGetSymbolAddress((void**)&xdbc, g_xdbc);
    cudaGetSymbolAddress((void**)&dcb,  g_dc);
    cudaGetSymbolAddress((void**)&dub,  g_du);

    cudaFuncSetAttribute((const void*)gemm_mma<0,1>, cudaFuncAttributeMaxDynamicSharedMemorySize, GSMEM);
    cudaFuncSetAttribute((const void*)gemm_mma<1,3>, cudaFuncAttributeMaxDynamicSharedMemorySize, GSMEM);
    cudaFuncSetAttribute((const void*)gemm_mma<2,1>, cudaFuncAttributeMaxDynamicSharedMemorySize, GSMEM);
    cudaFuncSetAttribute((const void*)gemm_mma<4,3>, cudaFuncAttributeMaxDynamicSharedMemorySize, GSMEM);

    // 0. fused init: weight prep + xdbc zero + rmsnorm
    init_fused<<<WPB + ZB + MROWS, 256>>>((const float4*)in_proj_w, (const float4*)out_proj_w,
                                          (const float4*)x_proj_w,  (const float4*)dt_proj_w,
                                          x, norm_w);

    // 1. in_proj (1-term fp16) -> xzx fp32 + sg fp16
    gemm_mma<0,1><<<dim3(32, 32, 1), 256, GSMEM>>>(xnh, xnh, inwh, inwh,
        D_MODEL, 2*D_INNER, D_INNER, xzx, nullptr, nullptr, nullptr, sgp);

    // 2. tiled conv + silu -> xch/xcl fp16
    conv_tiled<<<(MROWS/64) * 16, 256>>>(conv_w, conv_b);

    // 3. x_proj (3-term, split-K=8, atomics)
    gemm_mma<4,3><<<dim3(1, 32, 8), 256, GSMEM>>>(xch, xcl, xpwh, xpwl,
        D_INNER, 96, 96, xdbc, nullptr, nullptr, nullptr, nullptr);

    // 3b. dt hi/lo split
    dtsplit_kernel<<<(MROWS*DT_RANK + 255)/256, 256>>>();

    // 4. dt_proj (3-term) + softplus/clip/du epilogue (du from fp16 xch)
    gemm_mma<1,3><<<dim3(16, 32, 1), 256, GSMEM>>>(dth, dtl, dtwh, dtwl,
        DT_RANK, D_INNER, D_INNER, dcb, dub, dt_proj_b, xch, nullptr);

    // 5. selective scan
    scan_kernel<<<NB * (D_INNER/16), 256>>>(A_log, Dp);

    // 6. out_proj (1-term fp16) + residual
    gemm_mma<2,1><<<dim3(8, 32, 1), 256, GSMEM>>>(yh, yh, opwh, opwh,
        D_INNER, D_MODEL, D_MODEL, out, nullptr, x, nullptr, nullptr);
}

// round 10
// speedup vs baseline: 1.4473x; 1.4473x over previous
#include <cuda_runtime.h>
#include <cuda_fp16.h>
#include <math.h>
#include <stdint.h>

#define D_MODEL 1024
#define D_INNER 2048
#define D_STATE 16
#define DT_RANK 64
#define NB 2
#define TSEQ 2048
#define MROWS (NB*TSEQ)   /* 4096 */
#define EPSV 1e-6f

typedef __half fp16;

// ---------------- scratch (no allocations allowed) ----------------
__device__ fp16  g_xnh[MROWS*D_MODEL];
__device__ fp16  g_inwh[2*D_INNER*D_MODEL];
__device__ fp16  g_xpwh[96*D_INNER];
__device__ fp16  g_dtwh[D_INNER*DT_RANK];
__device__ fp16  g_opwh[D_MODEL*D_INNER];
__device__ float g_xz[MROWS*2*D_INNER];
__device__ float g_xconv[MROWS*D_INNER];
__device__ fp16  g_xch[MROWS*D_INNER],  g_xcl[MROWS*D_INNER];
__device__ float g_xdbc[MROWS*96];
__device__ fp16  g_dth[MROWS*DT_RANK],  g_dtl[MROWS*DT_RANK];
__device__ float g_dc[MROWS*D_INNER];
__device__ fp16  g_yh[MROWS*D_INNER];

// ---------------- helpers ----------------
__device__ __forceinline__ uint32_t s2u(const void* p) {
    uint32_t a;
    asm("{ .reg .u64 t; cvta.to.shared.u64 t, %1; cvt.u32.u64 %0, t; }" : "=r"(a) : "l"(p));
    return a;
}
__device__ __forceinline__ void cpa16(uint32_t dst, const void* src) {
    asm volatile("cp.async.cg.shared.global [%0], [%1], 16;" :: "r"(dst), "l"(src) : "memory");
}
__device__ __forceinline__ void cpa16z(uint32_t dst, const void* src, int sz) {
    asm volatile("cp.async.cg.shared.global [%0], [%1], 16, %2;" :: "r"(dst), "l"(src), "r"(sz) : "memory");
}
#define CPA_COMMIT() asm volatile("cp.async.commit_group;" ::: "memory")

#define LDSM4(r, a) \
    asm volatile("ldmatrix.sync.aligned.m8n8.x4.shared.b16 {%0,%1,%2,%3}, [%4];" \
        : "=r"((r)[0]),"=r"((r)[1]),"=r"((r)[2]),"=r"((r)[3]) : "r"(a))

#define MMA16816(d, a, b0, b1) \
    asm volatile("mma.sync.aligned.m16n8k16.row.col.f32.f16.f16.f32 " \
        "{%0,%1,%2,%3}, {%4,%5,%6,%7}, {%8,%9}, {%0,%1,%2,%3};" \
        : "+f"((d)[0]),"+f"((d)[1]),"+f"((d)[2]),"+f"((d)[3]) \
        : "r"((a)[0]),"r"((a)[1]),"r"((a)[2]),"r"((a)[3]), "r"(b0),"r"(b1))

// ---------------- split-fp16 GEMM via mma.sync ----------------
// 128x128 tile, BK=64, 3-stage ring (96KB) -> 2 CTAs/SM, 8 warps (2x4).
// TERMS=1: Ah*Bh    TERMS=2: Ah*Bh, Al*Bh
// EPI 0: C=v   EPI 1: dc = clip(softplus(v+bias))   EPI 2: C=v+res   EPI 4: atomicAdd
#define GSMEM (3 * 32768)
template<int EPI, int TERMS>
__global__ __launch_bounds__(256, 2)
void gemm_mma(const fp16* __restrict__ Ah, const fp16* __restrict__ Al,
              const fp16* __restrict__ Bh,
              int K, int Nreal, int ldc,
              float* __restrict__ o0,
              const float* __restrict__ e0)
{
    extern __shared__ char dyn[];
    const uint32_t sbase = s2u(dyn);
    const int tid = threadIdx.x, lane = tid & 31, wid = tid >> 5;
    const int wm = wid >> 2, wn = wid & 3;
    const int m0 = blockIdx.y * 128, n0 = blockIdx.x * 128;
    const int NCtot = TERMS * K / 64;
    const int per = (NCtot + gridDim.z - 1) / gridDim.z;
    const int kc0 = blockIdx.z * per;
    const int kc1 = min(NCtot, kc0 + per);

    float acc[4][4][4];
    #pragma unroll
    for (int i = 0; i < 4; i++)
        #pragma unroll
        for (int j = 0; j < 4; j++)
            #pragma unroll
            for (int k = 0; k < 4; k++) acc[i][j][k] = 0.f;

    auto load_stage = [&](int s, int kc) {
        int kb = kc * 64;
        int seg = (TERMS == 1) ? 0 : kb / K;
        int kk = kb - seg * K;
        const fp16* Asrc = (seg == 1) ? Al : Ah;
        uint32_t st = sbase + s * 32768;
        #pragma unroll
        for (int j = 0; j < 4; j++) {
            int idx = tid + j * 256;
            int r = idx >> 3, c = idx & 7;
            cpa16(st + r * 128 + ((c ^ (r & 7)) * 16),
                  Asrc + (size_t)(m0 + r) * K + kk + c * 8);
        }
        uint32_t sb = st + 16384;
        #pragma unroll
        for (int j = 0; j < 4; j++) {
            int idx = tid + j * 256;
            int r = idx >> 3, c = idx & 7;
            int nr = n0 + r;
            int ok = nr < Nreal;
            cpa16z(sb + r * 128 + ((c ^ (r & 7)) * 16),
                   Bh + (size_t)(ok ? nr : 0) * K + kk + c * 8, ok ? 16 : 0);
        }
    };

    if (kc0 < kc1)     load_stage(0, kc0);
    CPA_COMMIT();
    if (kc0 + 1 < kc1) load_stage(1, kc0 + 1);
    CPA_COMMIT();

    for (int kc = kc0; kc < kc1; kc++) {
        int i = kc - kc0;
        int s = i % 3;
        asm volatile("cp.async.wait_group 1;" ::: "memory");
        __syncthreads();
        if (kc + 2 < kc1) load_stage((i + 2) % 3, kc + 2);
        CPA_COMMIT();

        uint32_t sA = sbase + s * 32768;
        uint32_t sB = sA + 16384;
        #pragma unroll
        for (int ks = 0; ks < 4; ks++) {
            uint32_t a[4][4], b[2][4];
            #pragma unroll
            for (int mi = 0; mi < 4; mi++) {
                int r = wm * 64 + mi * 16 + (lane & 15);
                int c = (2 * ks + (lane >> 4)) ^ (r & 7);
                LDSM4(a[mi], sA + r * 128 + c * 16);
            }
            #pragma unroll
            for (int g = 0; g < 2; g++) {
                int r = wn * 32 + g * 16 + (lane & 7) + ((lane >> 4) & 1) * 8;
                int c = (2 * ks + ((lane >> 3) & 1)) ^ (r & 7);
                LDSM4(b[g], sB + r * 128 + c * 16);
            }
            #pragma unroll
            for (int mi = 0; mi < 4; mi++)
                #pragma unroll
                for (int nj = 0; nj < 4; nj++) {
                    int bg = nj >> 1, br = (nj & 1) * 2;
                    MMA16816(acc[mi][nj], a[mi], b[bg][br], b[bg][br+1]);
                }
        }
    }

    // ---- epilogue straight from registers (float2 pairs) ----
    #pragma unroll
    for (int mi = 0; mi < 4; mi++)
        #pragma unroll
        for (int nj = 0; nj < 4; nj++)
            #pragma unroll
            for (int h = 0; h < 2; h++) {
                int m = m0 + wm*64 + mi*16 + (lane >> 2) + h*8;
                int nb = n0 + wn*32 + nj*8 + (lane & 3)*2;
                float vx = acc[mi][nj][h*2], vy = acc[mi][nj][h*2+1];
                size_t ci = (size_t)m * ldc + nb;
                if (EPI == 0) {
                    *(float2*)(o0 + ci) = make_float2(vx, vy);
                } else if (EPI == 1) {
                    vx += e0[nb]; vy += e0[nb+1];
                    float spx = (vx > 20.f) ? vx : log1pf(__expf(vx));
                    float spy = (vy > 20.f) ? vy : log1pf(__expf(vy));
                    float dx = fminf(fmaxf(spx, -10.f), 1.f);
                    float dy = fminf(fmaxf(spy, -10.f), 1.f);
                    *(float2*)(o0 + ci) = make_float2(dx, dy);
                } else if (EPI == 2) {
                    float2 rv = *(const float2*)(e0 + ci);
                    *(float2*)(o0 + ci) = make_float2(vx + rv.x, vy + rv.y);
                } else {
                    if (nb < Nreal) {
                        atomicAdd(o0 + ci, vx);
                        atomicAdd(o0 + ci + 1, vy);
                    }
                }
            }
}

// ---------------- fused init: wprep(hi-only) + zero(xdbc) + rmsnorm ----------------
#define C1 (2*D_INNER*D_MODEL/4)
#define C2 (C1 + D_MODEL*D_INNER/4)
#define C3 (C2 + 96*D_INNER/4)
#define C4 (C3 + D_INNER*DT_RANK/4)
#define WPB ((C4 + 255) / 256)
#define ZB  ((MROWS*96) / 256)
__global__ void init_fused(const float4* __restrict__ w_in,
                           const float4* __restrict__ w_op,
                           const float4* __restrict__ w_xp,
                           const float4* __restrict__ w_dt,
                           const float* __restrict__ x,
                           const float* __restrict__ w_norm) {
    __shared__ float red[8];
    __shared__ float sscale;
    int bx = blockIdx.x;
    if (bx < WPB) {
        int i = bx * 256 + threadIdx.x;
        if (i >= C4) return;
        const float4* src;
        fp16* hi;
        int j = i;
        if (i < C1)      { src = w_in; hi = g_inwh; }
        else if (i < C2) { src = w_op; hi = g_opwh; j = i - C1; }
        else if (i < C3) { src = w_xp; hi = g_xpwh; j = i - C2; }
        else             { src = w_dt; hi = g_dtwh; j = i - C3; }
        float4 v = src[j];
        __half2 p0, p1;
        p0.x = __float2half(v.x); p0.y = __float2half(v.y);
        p1.x = __float2half(v.z); p1.y = __float2half(v.w);
        *(__half2*)(hi + (size_t)j * 4)     = p0;
        *(__half2*)(hi + (size_t)j * 4 + 2) = p1;
    } else if (bx < WPB + ZB) {
        int i = (bx - WPB) * 256 + threadIdx.x;
        g_xdbc[i] = 0.f;
    } else {
        int row = bx - WPB - ZB;
        int tid = threadIdx.x;
        const float4* xr = (const float4*)(x + (size_t)row * D_MODEL);
        float4 v = xr[tid];
        float ss = v.x*v.x + v.y*v.y + v.z*v.z + v.w*v.w;
        #pragma unroll
        for (int off = 16; off > 0; off >>= 1)
            ss += __shfl_xor_sync(0xffffffffu, ss, off);
        int lane = tid & 31, wq = tid >> 5;
        if (lane == 0) red[wq] = ss;
        __syncthreads();
        if (tid == 0) {
            float t = 0.f;
            #pragma unroll
            for (int i2 = 0; i2 < 8; i2++) t += red[i2];
            sscale = rsqrtf(t * (1.0f / D_MODEL) + EPSV);
        }
        __syncthreads();
        float sc = sscale;
        float4 wv = ((const float4*)w_norm)[tid];
        float o0 = v.x*sc*wv.x, o1 = v.y*sc*wv.y, o2 = v.z*sc*wv.z, o3 = v.w*sc*wv.w;
        size_t base = (size_t)row * D_MODEL + tid * 4;
        __half2 ph0, ph1;
        ph0.x = __float2half(o0); ph0.y = __float2half(o1);
        ph1.x = __float2half(o2); ph1.y = __float2half(o3);
        *(__half2*)(g_xnh+base)   = ph0; *(__half2*)(g_xnh+base+2) = ph1;
    }
}

__global__ void dtsplit_kernel() {
    int i = blockIdx.x * 256 + threadIdx.x;
    if (i >= MROWS * DT_RANK) return;
    int m = i >> 6, n = i & 63;
    float v = g_xdbc[(size_t)m * 96 + n];
    fp16 h = __float2half(v);
    g_dth[i] = h;
    g_dtl[i] = __float2half(v - __half2float(h));
}

// ---------------- depthwise causal conv(4) + silu (+fp16 split) ----------------
__global__ void conv_silu_kernel(const float* __restrict__ cw,
                                 const float* __restrict__ cb) {
    int idx = blockIdx.x * 256 + threadIdx.x;
    if (idx >= MROWS * (D_INNER/4)) return;
    int d4 = idx & (D_INNER/4 - 1);
    int bt = idx >> 9;
    int t  = bt & (TSEQ - 1);
    int d  = d4 * 4;
    float wv[4][4];
    *(float4*)wv[0] = *(const float4*)(cw + (d+0)*4);
    *(float4*)wv[1] = *(const float4*)(cw + (d+1)*4);
    *(float4*)wv[2] = *(const float4*)(cw + (d+2)*4);
    *(float4*)wv[3] = *(const float4*)(cw + (d+3)*4);
    float4 bvv = *(const float4*)(cb + d);
    float a0 = bvv.x, a1 = bvv.y, a2 = bvv.z, a3 = bvv.w;
    #pragma unroll
    for (int k = 0; k < 4; k++) {
        int tt = t - 3 + k;
        if (tt < 0) continue;
        const float4 xv = *(const float4*)(g_xz + (size_t)(bt - t + tt) * (2*D_INNER) + d);
        a0 = fmaf(wv[0][k], xv.x, a0);
        a1 = fmaf(wv[1][k], xv.y, a1);
        a2 = fmaf(wv[2][k], xv.z, a2);
        a3 = fmaf(wv[3][k], xv.w, a3);
    }
    float o0 = a0/(1.f+__expf(-a0)), o1 = a1/(1.f+__expf(-a1));
    float o2 = a2/(1.f+__expf(-a2)), o3 = a3/(1.f+__expf(-a3));
    size_t base = (size_t)bt * D_INNER + d;
    *(float4*)(g_xconv + base) = make_float4(o0,o1,o2,o3);
    fp16 h0=__float2half(o0), h1=__float2half(o1), h2=__float2half(o2), h3=__float2half(o3);
    __half2 ph0, ph1, pl0, pl1;
    ph0.x=h0; ph0.y=h1; ph1.x=h2; ph1.y=h3;
    pl0.x=__float2half(o0-__half2float(h0));
    pl0.y=__float2half(o1-__half2float(h1));
    pl1.x=__float2half(o2-__half2float(h2));
    pl1.y=__float2half(o3-__half2float(h3));
    *(__half2*)(g_xch+base)   = ph0; *(__half2*)(g_xch+base+2) = ph1;
    *(__half2*)(g_xcl+base)   = pl0; *(__half2*)(g_xcl+base+2) = pl1;
}

// ---------------- selective scan (latency-optimized; du computed in staging) ----------------
__global__ __launch_bounds__(256) void scan_kernel(const float* __restrict__ A_log,
                                                   const float* __restrict__ Dp) {
    __shared__ float sB[64*16], sC[64*16], sdc[64*16], sdu[64*16];
    __shared__ float se[64*16], sg[64*16];
    __shared__ float sP[16*16*17];
    int bid = blockIdx.x;
    int b = bid >> 7;
    int d0 = (bid & 127) << 4;
    int tid = threadIdx.x;
    int w = tid >> 5, lane = tid & 31;
    int s = lane & 15, half = lane >> 4;
    int cl = w * 2 + half;
    int d = d0 + cl;
    int jlo = tid & 15;
    int tl_r = tid >> 4, cl_r = tid & 15;
    float Aval = -__expf(A_log[d * D_STATE + s]);
    float Dvj = Dp[d0 + jlo];
    float h = 0.f;

    for (int t0 = 0; t0 < TSEQ; t0 += 64) {
        for (int i = tid; i < 1024; i += 256) {
            int ti = i >> 4, j = i & 15;
            size_t row = (size_t)b * TSEQ + t0 + ti;
            sB[i]  = g_xdbc[row * 96 + 64 + j];
            sC[i]  = g_xdbc[row * 96 + 80 + j];
            float dcv = g_dc[row * D_INNER + d0 + j];
            float xcv = g_xconv[row * D_INNER + d0 + j];
            sdc[i] = dcv;
            sdu[i] = dcv * xcv;
            se[i]  = xcv * Dvj;
            float zv = g_xz[row * (2*D_INNER) + D_INNER + d0 + j];
            sg[i]  = zv / (1.f + __expf(-zv));
        }
        __syncthreads();
        #pragma unroll
        for (int sub = 0; sub < 4; sub++) {
            #pragma unroll
            for (int i = 0; i < 16; i++) {
                int t = sub * 16 + i;
                float dcv = sdc[t*16 + cl];
                float duv = sdu[t*16 + cl];
                float r = __expf(dcv * Aval);
                h = fmaf(r, h, duv * sB[t*16 + s]);
                sP[(i*16 + cl)*17 + s] = h * sC[t*16 + s];
            }
            __syncthreads();
            {
                float p = 0.f;
                int base = (tl_r*16 + cl_r)*17;
                #pragma unroll
                for (int q = 0; q < 16; q++) p += sP[base + q];
                int t = sub * 16 + tl_r;
                float yv = (p + se[t*16 + cl_r]) * sg[t*16 + cl_r];
                size_t row = (size_t)b * TSEQ + t0 + t;
                g_yh[row * D_INNER + d0 + cl_r] = __float2half(yv);
            }
            __syncthreads();
        }
    }
}

// ---------------- launch ----------------
extern "C" void kernel_launch(void* const* d_in, const int* in_sizes, int n_in,
                              void* d_out, int out_size) {
    (void)in_sizes; (void)n_in; (void)out_size;
    const float* x          = (const float*)d_in[0];
    const float* in_proj_w  = (const float*)d_in[1];
    const float* conv_w     = (const float*)d_in[2];
    const float* conv_b     = (const float*)d_in[3];
    const float* x_proj_w   = (const float*)d_in[4];
    const float* dt_proj_w  = (const float*)d_in[5];
    const float* dt_proj_b  = (const float*)d_in[6];
    const float* A_log      = (const float*)d_in[7];
    const float* Dp         = (const float*)d_in[8];
    const float* out_proj_w = (const float*)d_in[9];
    const float* norm_w     = (const float*)d_in[10];
    float* out = (float*)d_out;

    fp16 *xnh, *inwh, *xpwh, *dtwh, *opwh;
    fp16 *xch, *xcl, *dth, *dtl, *yh;
    float *xz, *xdbc, *dcb;
    cudaGetSymbolAddress((void**)&xnh,  g_xnh);
    cudaGetSymbolAddress((void**)&inwh, g_inwh);
    cudaGetSymbolAddress((void**)&xpwh, g_xpwh);
    cudaGetSymbolAddress((void**)&dtwh, g_dtwh);
    cudaGetSymbolAddress((void**)&opwh, g_opwh);
    cudaGetSymbolAddress((void**)&xch,  g_xch);  cudaGetSymbolAddress((void**)&xcl,  g_xcl);
    cudaGetSymbolAddress((void**)&dth,  g_dth);  cudaGetSymbolAddress((void**)&dtl,  g_dtl);
    cudaGetSymbolAddress((void**)&yh,   g_yh);
    cudaGetSymbolAddress((void**)&xz,   g_xz);
    cudaGetSymbolAddress((void**)&xdbc, g_xdbc);
    cudaGetSymbolAddress((void**)&dcb,  g_dc);

    cudaFuncSetAttribute((const void*)gemm_mma<0,1>, cudaFuncAttributeMaxDynamicSharedMemorySize, GSMEM);
    cudaFuncSetAttribute((const void*)gemm_mma<1,2>, cudaFuncAttributeMaxDynamicSharedMemorySize, GSMEM);
    cudaFuncSetAttribute((const void*)gemm_mma<2,1>, cudaFuncAttributeMaxDynamicSharedMemorySize, GSMEM);
    cudaFuncSetAttribute((const void*)gemm_mma<4,2>, cudaFuncAttributeMaxDynamicSharedMemorySize, GSMEM);

    // 0. fused init: weight prep (hi only) + xdbc zero + rmsnorm
    init_fused<<<WPB + ZB + MROWS, 256>>>((const float4*)in_proj_w, (const float4*)out_proj_w,
                                          (const float4*)x_proj_w,  (const float4*)dt_proj_w,
                                          x, norm_w);

    // 1. in_proj (1-term fp16) -> xz fp32
    gemm_mma<0,1><<<dim3(32, 32, 1), 256, GSMEM>>>(xnh, xnh, inwh,
        D_MODEL, 2*D_INNER, 2*D_INNER, xz, nullptr);

    // 2. conv + silu -> xconv fp32 + xch/xcl fp16
    conv_silu_kernel<<<(MROWS * (D_INNER/4) + 255)/256, 256>>>(conv_w, conv_b);

    // 3. x_proj (2-term, split-K=8, atomics into zeroed xdbc)
    gemm_mma<4,2><<<dim3(1, 32, 8), 256, GSMEM>>>(xch, xcl, xpwh,
        D_INNER, 96, 96, xdbc, nullptr);

    // 3b. dt hi/lo split
    dtsplit_kernel<<<(MROWS*DT_RANK + 255)/256, 256>>>();

    // 4. dt_proj (2-term) + softplus/clip epilogue -> dc only
    gemm_mma<1,2><<<dim3(16, 32, 1), 256, GSMEM>>>(dth, dtl, dtwh,
        DT_RANK, D_INNER, D_INNER, dcb, dt_proj_b);

    // 5. selective scan (du = dc*xconv computed in staging)
    scan_kernel<<<NB * (D_INNER/16), 256>>>(A_log, Dp);

    // 6. out_proj (1-term fp16) + residual
    gemm_mma<2,1><<<dim3(8, 32, 1), 256, GSMEM>>>(yh, yh, opwh,
        D_INNER, D_MODEL, D_MODEL, out, x);
}